// round 15
// baseline (speedup 1.0000x reference)
#include <cuda_runtime.h>
#include <cuda_bf16.h>
#include <cstdint>

#define NN   128            // state size
#define NB   2              // batch
#define LL   2048           // sequence length
#define TC   16             // chunk length
#define KC   (LL / TC)      // 128 chunks per batch
#define NG   8              // chunks per group
#define GG   (KC / NG)      // 16 groups per batch
#define PBLK 384            // prologue grid size (must be <= resident capacity)

// ---------------- device scratch ----------------
__device__ double g_ATd[NN * NN];     // A transposed, fp64
__device__ float  g_AdT[NN * NN];     // AdT[k*128+j] = Ad[j][k]
__device__ float  g_Bd[NN];
__device__ float  g_PT[NN * NN];      // P = Ad^16, transposed layout
__device__ float  g_QT[NN * NN];      // Q = P^8 = Ad^128, transposed layout
__device__ float  g_locend[NB * KC * NN];   // chunk-local end states
__device__ float  g_gle[NB * GG * NN];      // group-local end states
__device__ float  g_carry[NB * KC * NN];    // chunk entry states
__device__ unsigned long long g_sync = 0ULL; // monotonic grid-barrier counter

// Device-wide barrier for a 384-block grid with ALL blocks resident.
// Counter is never reset: each launch performs 4 barriers -> +4*384, so the
// value at every launch start is a multiple of 384; per barrier all blocks'
// fetched 'old' values lie in one 384-aligned window -> same target.
__device__ __forceinline__ void gsync() {
    __syncthreads();
    __threadfence();
    if (threadIdx.x == 0) {
        unsigned long long old = atomicAdd(&g_sync, 1ULL);
        unsigned long long tgt = (old / PBLK + 1ULL) * PBLK;
        while (*(volatile unsigned long long*)&g_sync < tgt) { }
    }
    __syncthreads();
}

// ---------------- canonical serial-matvec pieces (128 thr, 1 bar/step) --------
__device__ __forceinline__ void load_row(float* ad, const float* __restrict__ M,
                                         int j) {
#pragma unroll
    for (int k = 0; k < NN; k++) ad[k] = M[k * NN + j];
}

__device__ __forceinline__ float dot128(const float* __restrict__ ad,
                                        const float* __restrict__ csh) {
    const float4* c4 = (const float4*)csh;
    float a0 = 0.f, a1 = 0.f, a2 = 0.f, a3 = 0.f;
#pragma unroll
    for (int k4 = 0; k4 < 32; k4++) {
        float4 cv = c4[k4];
        a0 = fmaf(ad[4 * k4 + 0], cv.x, a0);
        a1 = fmaf(ad[4 * k4 + 1], cv.y, a1);
        a2 = fmaf(ad[4 * k4 + 2], cv.z, a2);
        a3 = fmaf(ad[4 * k4 + 3], cv.w, a3);
    }
    return (a0 + a1) + (a2 + a3);
}

// ---------------- fused prologue: 5 phases, 4 grid barriers -------------------
// P0 transpose (16 blk) | P1 disc (129 blk) | P2 chain (384 blk)
// P3 powgroup (160 blk) | P4 carryBC (32 blk)
__global__ void __launch_bounds__(NN, 3) k_prologue(const float* __restrict__ A,
                                                    const float* __restrict__ B,
                                                    const float* __restrict__ f,
                                                    float* __restrict__ cfin) {
    __shared__ __align__(16) float sh[2336];   // 9.3 KB, reused per phase
    float* cur = sh;                  // [2][NN]
    float* add = sh + 2 * NN;         // [GG][NN]
    float* fsh = sh + 2 * NN + GG * NN;   // [TC]
    int tid = threadIdx.x, blk = blockIdx.x;

    // ---- P0: transpose A -> fp64 g_ATd (16 blocks, 32x32 tiles) ----
    if (blk < 16) {
        int bx = (blk & 3) * 32, by = (blk >> 2) * 32;
        int tx = tid & 31, ty = tid >> 5;
        float* tile = sh;                       // 1056 floats
        for (int r = ty; r < 32; r += 4)
            tile[r * 33 + tx] = A[(by + r) * NN + bx + tx];
        __syncthreads();
        for (int r = ty; r < 32; r += 4)
            g_ATd[(bx + r) * NN + by + tx] = (double)tile[tx * 33 + r];
    }
    gsync();

    // ---- P1: discretize (fp64 forward substitution, R5-proven) ----
    if (blk < NN + 1) {
        double* dinv = (double*)sh;             // 128 doubles
        double* xsh  = (double*)sh + NN;        // 2 doubles
        int c = blk, i = tid;
        dinv[i] = 1.0 / (1.0 - 0.5 * g_ATd[i * NN + i]);
        double ri;
        if (c < NN) ri = (i == c ? 1.0 : 0.0) + 0.5 * g_ATd[c * NN + i];
        else        ri = (double)B[i];
        double a_next = 0.5 * g_ATd[0 * NN + i];
        __syncthreads();
        for (int jj = 0; jj < NN; jj++) {
            double aj = a_next;
            if (jj + 1 < NN) a_next = 0.5 * g_ATd[(jj + 1) * NN + i];
            if (i == jj) xsh[jj & 1] = ri * dinv[jj];
            __syncthreads();
            double x = xsh[jj & 1];
            if (i > jj)       ri = fma(aj, x, ri);
            else if (i == jj) ri = x;
        }
        if (c < NN) g_AdT[c * NN + i] = (float)ri;
        else        g_Bd[i] = (float)ri;
    }
    gsync();

    // ---- P2: chunk locals (256 blk) + P=Ad^16 columns (128 blk) ----
    {
        int j = tid;
        float mrow[NN]; load_row(mrow, g_AdT, j);
        if (blk < NB * KC) {
            int b = blk >> 7, ch = blk & (KC - 1);
            float bd = g_Bd[j];
            if (j < TC) fsh[j] = f[b * LL + ch * TC + j];
            cur[j] = 0.f;
            __syncthreads();
            float nc = 0.f;
            for (int s = 0; s < TC; s++) {
                float d = dot128(mrow, cur + (s & 1) * NN);
                nc = fmaf(bd, fsh[s], d);
                cur[((s + 1) & 1) * NN + j] = nc;
                __syncthreads();
            }
            g_locend[(b * KC + ch) * NN + j] = nc;
        } else {
            int j0 = blk - NB * KC;
            cur[j] = (j == j0) ? 1.f : 0.f;
            __syncthreads();
            float nc = 0.f;
            for (int s = 0; s < TC; s++) {
                nc = dot128(mrow, cur + (s & 1) * NN);
                cur[((s + 1) & 1) * NN + j] = nc;
                __syncthreads();
            }
            g_PT[j0 * NN + j] = nc;             // P[j][j0]
        }
    }
    gsync();

    // ---- P3: Q=P^8 columns (128 blk) + group-local scans (32 blk) ----
    if (blk < NN + NB * GG) {
        int j = tid;
        float mrow[NN]; load_row(mrow, g_PT, j);
        if (blk < NN) {
            int j0 = blk;
            cur[j] = (j == j0) ? 1.f : 0.f;
            __syncthreads();
            float nc = 0.f;
            for (int s = 0; s < NG; s++) {
                nc = dot128(mrow, cur + (s & 1) * NN);
                cur[((s + 1) & 1) * NN + j] = nc;
                __syncthreads();
            }
            g_QT[j0 * NN + j] = nc;
        } else {
            int gb = blk - NN;                   // 0..31
            int b = gb >> 4, g = gb & (GG - 1);
            for (int s = 0; s < NG; s++)
                add[s * NN + j] = g_locend[(b * KC + g * NG + s) * NN + j];
            cur[j] = 0.f;
            __syncthreads();
            float nc = 0.f;
            for (int s = 0; s < NG; s++) {
                float d = dot128(mrow, cur + (s & 1) * NN);
                nc = d + add[s * NN + j];
                cur[((s + 1) & 1) * NN + j] = nc;
                __syncthreads();
            }
            g_gle[(b * GG + g) * NN + j] = nc;
        }
    }
    gsync();

    // ---- P4: fused carry (32 blk): Q-scan for group entry, then P-chain ----
    if (blk < NB * GG) {
        int j = tid;
        int b = blk >> 4, g = blk & (GG - 1);
        float mrow[NN]; load_row(mrow, g_QT, j);

        int nload = (g == GG - 1) ? GG : g;
        for (int s = 0; s < nload; s++)
            add[s * NN + j] = g_gle[(b * GG + s) * NN + j];
        cur[j] = 0.f;
        __syncthreads();

        int buf = 0;
        for (int gg = 0; gg < g; gg++) {
            float d = dot128(mrow, cur + buf * NN);
            float nc = d + add[gg * NN + j];
            buf ^= 1;
            cur[buf * NN + j] = nc;
            __syncthreads();
        }
        if (g == GG - 1 && cfin != nullptr) {
            float d = dot128(mrow, cur + buf * NN);
            cfin[b * NN + j] = d + add[(GG - 1) * NN + j];
        }

        load_row(mrow, g_PT, j);
        for (int s = 0; s < NG - 1; s++)
            add[s * NN + j] = g_locend[(b * KC + g * NG + s) * NN + j];
        float e = cur[buf * NN + j];
        g_carry[(b * KC + g * NG) * NN + j] = e;
        __syncthreads();

        for (int c2 = 1; c2 < NG; c2++) {
            float d = dot128(mrow, cur + buf * NN);
            float nc = d + add[(c2 - 1) * NN + j];
            buf ^= 1;
            cur[buf * NN + j] = nc;
            g_carry[(b * KC + g * NG + c2) * NN + j] = nc;
            __syncthreads();
        }
    }
}

// ---------------- fused states+expand (R12-proven, unchanged) -----------------
__global__ void __launch_bounds__(256) k_se(const float* __restrict__ f,
                                            const float* __restrict__ C,
                                            const float* __restrict__ D,
                                            float* __restrict__ y) {
    __shared__ float states[TC][NN];   // 8 KB
    __shared__ float cur[NN];
    __shared__ float part[NN];
    __shared__ float Csh[NN];
    __shared__ float fsh[TC];

    int tid = threadIdx.x;
    int ch = blockIdx.x, b = blockIdx.y;
    int j = tid & 127, h = tid >> 7;

    float ad[64];
#pragma unroll
    for (int k = 0; k < 64; k++) ad[k] = g_AdT[(h * 64 + k) * NN + j];
    float bd = (h == 0) ? g_Bd[j] : 0.f;

    if (tid < NN) {
        Csh[tid] = C[tid];
        cur[tid] = g_carry[(b * KC + ch) * NN + tid];
    }
    if (tid < TC) fsh[tid] = f[b * LL + ch * TC + tid];
    float Dv = D[0];
    __syncthreads();

    for (int s = 0; s < TC; s++) {
        const float4* c4 = (const float4*)cur + h * 16;
        float a0 = 0.f, a1 = 0.f, a2 = 0.f, a3 = 0.f;
#pragma unroll
        for (int k4 = 0; k4 < 16; k4++) {
            float4 cv = c4[k4];
            a0 = fmaf(ad[4 * k4 + 0], cv.x, a0);
            a1 = fmaf(ad[4 * k4 + 1], cv.y, a1);
            a2 = fmaf(ad[4 * k4 + 2], cv.z, a2);
            a3 = fmaf(ad[4 * k4 + 3], cv.w, a3);
        }
        float p = (a0 + a1) + (a2 + a3);
        if (h == 0) p = fmaf(bd, fsh[s], p);
        if (h == 1) part[j] = p;
        __syncthreads();
        if (h == 0) {
            float nc = p + part[j];
            states[s][j] = nc;
            cur[j] = nc;
        }
        __syncthreads();
    }

    size_t base = ((size_t)(b * LL + ch * TC)) * (NN * NN);
    for (int s = 0; s < TC; s++) {
        float df = Dv * fsh[s];
        float4* out = (float4*)(y + base + (size_t)s * (NN * NN));
        float4 cv = ((const float4*)states[s])[tid & 31];
        int n0 = tid >> 5;
#pragma unroll
        for (int it = 0; it < 16; it++) {
            float cn = Csh[n0 + 8 * it];
            float4 o;
            o.x = fmaf(cn, cv.x, df);
            o.y = fmaf(cn, cv.y, df);
            o.z = fmaf(cn, cv.z, df);
            o.w = fmaf(cn, cv.w, df);
            out[tid + 256 * it] = o;
        }
    }
}

// ---------------- launcher ----------------------------------------------------
extern "C" void kernel_launch(void* const* d_in, const int* in_sizes, int n_in,
                              void* d_out, int out_size) {
    const float* f = (const float*)d_in[0];
    const float* A = (const float*)d_in[1];
    const float* B = (const float*)d_in[2];
    const float* C = (const float*)d_in[3];
    const float* D = (const float*)d_in[4];

    const long long Y_ELEMS = (long long)NB * LL * NN * NN;   // 67,108,864
    long long off = (long long)out_size - Y_ELEMS;
    if (off < 0) off = 0;
    float* y    = (float*)d_out + off;
    float* cfin = (off >= NB * NN) ? (float*)d_out : nullptr;

    k_prologue<<<PBLK, NN>>>(A, B, f, cfin);
    k_se<<<dim3(KC, NB), 256>>>(f, C, D, y);
}